// round 1
// baseline (speedup 1.0000x reference)
#include <cuda_runtime.h>
#include <cstdint>
#include <cstddef>

// ---------------- problem constants ----------------
#define BB 16
#define N0 4096

// scratch (device globals; allocation-free per harness rules)
__device__ float  g_bufA[33554432];           // 128 MB  (max: 131072x256)
__device__ float  g_bufB[16777216];           // 64 MB   (max: 131072x128)
__device__ float  g_newxyz[BB * 256 * 3];
__device__ int    g_fidx[BB * 256];
__device__ int    g_gi[131072];               // max of 16*256*32 and 16*128*64
__device__ float  g_l1pt[BB * 256 * 128];     // l1 points, (b,s,c) layout
__device__ float  g_l2pt[BB * 128 * 256];     // l2 points, (b,s,c) layout
__device__ double g_sum[512];
__device__ double g_sumsq[512];
__device__ float  g_scale[512];
__device__ float  g_shift[512];

// ---------------- FPS: one block per batch ----------------
__global__ void fps_kernel(const float* __restrict__ xyz, int n, int npoint,
                           int* __restrict__ fidx, float* __restrict__ newxyz,
                           float* __restrict__ outxyz) {
    extern __shared__ float sm[];
    float* sx = sm;
    float* sy = sm + n;
    float* sz = sm + 2 * n;
    float* dist = sm + 3 * n;
    __shared__ float rv[16];
    __shared__ int   ri[16];
    __shared__ int   sfar;

    int b = blockIdx.x, tid = threadIdx.x, bt = blockDim.x;
    const float* base = xyz + (size_t)b * 3 * n;
    for (int i = tid; i < n; i += bt) {
        sx[i] = base[i];
        sy[i] = base[n + i];
        sz[i] = base[2 * n + i];
        dist[i] = 1e10f;
    }
    __syncthreads();

    int far = 0;
    for (int t = 0; t < npoint; t++) {
        float cx = sx[far], cy = sy[far], cz = sz[far];
        if (tid == 0) {
            fidx[b * npoint + t] = far;
            float* nw = &newxyz[(b * npoint + t) * 3];
            nw[0] = cx; nw[1] = cy; nw[2] = cz;
            outxyz[(size_t)b * 3 * npoint + t] = cx;
            outxyz[(size_t)b * 3 * npoint + npoint + t] = cy;
            outxyz[(size_t)b * 3 * npoint + 2 * npoint + t] = cz;
        }
        float bv = -1.0f;
        int bi = 0x7fffffff;
        for (int i = tid; i < n; i += bt) {
            float dx = __fsub_rn(sx[i], cx);
            float dy = __fsub_rn(sy[i], cy);
            float dz = __fsub_rn(sz[i], cz);
            float d = __fadd_rn(__fadd_rn(__fmul_rn(dx, dx), __fmul_rn(dy, dy)), __fmul_rn(dz, dz));
            float dd = fminf(dist[i], d);
            dist[i] = dd;
            if (dd > bv) { bv = dd; bi = i; }
        }
#pragma unroll
        for (int o = 16; o; o >>= 1) {
            float ov = __shfl_down_sync(0xffffffffu, bv, o);
            int   oi = __shfl_down_sync(0xffffffffu, bi, o);
            if (ov > bv || (ov == bv && oi < bi)) { bv = ov; bi = oi; }
        }
        if ((tid & 31) == 0) { rv[tid >> 5] = bv; ri[tid >> 5] = bi; }
        __syncthreads();
        if (tid < 32) {
            int nw = bt >> 5;
            float v = (tid < nw) ? rv[tid] : -2.0f;
            int  ii = (tid < nw) ? ri[tid] : 0x7fffffff;
#pragma unroll
            for (int o = 16; o; o >>= 1) {
                float ov = __shfl_down_sync(0xffffffffu, v, o);
                int   oi = __shfl_down_sync(0xffffffffu, ii, o);
                if (ov > v || (ov == v && oi < ii)) { v = ov; ii = oi; }
            }
            if (tid == 0) sfar = ii;
        }
        __syncthreads();
        far = sfar;
        __syncthreads();
    }
}

// ---------------- ball query: one warp per (b,s) ----------------
__global__ void ballquery_kernel(const float* __restrict__ xyz, const float* __restrict__ newxyz,
                                 int n, int S, int K, float r2, int* __restrict__ gi) {
    int gw = (blockIdx.x * blockDim.x + threadIdx.x) >> 5;
    int lane = threadIdx.x & 31;
    if (gw >= BB * S) return;
    int b = gw / S, s = gw % S;
    const float* nw = &newxyz[(b * S + s) * 3];
    float nx = nw[0], ny = nw[1], nz = nw[2];
    float nsq = __fadd_rn(__fadd_rn(__fmul_rn(nx, nx), __fmul_rn(ny, ny)), __fmul_rn(nz, nz));
    const float* px = xyz + (size_t)b * 3 * n;
    int* g = gi + (size_t)(b * S + s) * K;
    int cnt = 0, first = -1;
    for (int base = 0; base < n && cnt < K; base += 32) {
        int i = base + lane;
        float x = px[i], y = px[n + i], z = px[2 * n + i];
        float psq = __fadd_rn(__fadd_rn(__fmul_rn(x, x), __fmul_rn(y, y)), __fmul_rn(z, z));
        float dot = __fadd_rn(__fadd_rn(__fmul_rn(nx, x), __fmul_rn(ny, y)), __fmul_rn(nz, z));
        float sqr = __fsub_rn(__fadd_rn(nsq, psq), __fmul_rn(2.0f, dot));
        bool ok = !(sqr > r2);
        unsigned m = __ballot_sync(0xffffffffu, ok);
        if (first < 0 && m) first = base + __ffs(m) - 1;
        int pos = cnt + __popc(m & ((1u << lane) - 1u));
        if (ok && pos < K) g[pos] = i;
        cnt += __popc(m);
    }
    if (cnt > K) cnt = K;
    for (int p = cnt + lane; p < K; p += 32) g[p] = first;
}

// ---------------- gathers ----------------
__global__ void gather_sa1(const float* __restrict__ xyz, const float* __restrict__ pts,
                           const int* __restrict__ gi, const float* __restrict__ newxyz,
                           float* __restrict__ out) {
    int row = blockIdx.x * blockDim.x + threadIdx.x;
    if (row >= BB * 256 * 32) return;
    int s = (row >> 5) & 255, b = row >> 13;
    int idx = gi[row];
    const float* nw = &newxyz[(b * 256 + s) * 3];
    const float* px = xyz + (size_t)b * 3 * N0;
    const float* pp = pts + (size_t)b * 3 * N0;
    float* o = out + (size_t)row * 6;
    o[0] = __fsub_rn(px[idx], nw[0]);
    o[1] = __fsub_rn(px[N0 + idx], nw[1]);
    o[2] = __fsub_rn(px[2 * N0 + idx], nw[2]);
    o[3] = pp[idx];
    o[4] = pp[N0 + idx];
    o[5] = pp[2 * N0 + idx];
}

__global__ void gather_sa2(const float* __restrict__ l1xyz, const float* __restrict__ l1pt,
                           const int* __restrict__ gi, const float* __restrict__ newxyz,
                           float* __restrict__ out) {
    const int S = 128, K = 64, C = 131;
    int gw = (blockIdx.x * blockDim.x + threadIdx.x) >> 5;
    int lane = threadIdx.x & 31;
    if (gw >= BB * S * K) return;
    int s = (gw / K) % S, b = gw / (S * K);
    int idx = gi[gw];
    float* o = out + (size_t)gw * C;
    for (int c = lane; c < C; c += 32) {
        float v;
        if (c < 3)
            v = __fsub_rn(l1xyz[(size_t)b * 768 + c * 256 + idx], newxyz[(b * S + s) * 3 + c]);
        else
            v = l1pt[((size_t)b * 256 + idx) * 128 + (c - 3)];
        o[c] = v;
    }
}

__global__ void gather_sa3(const float* __restrict__ l2xyz, const float* __restrict__ l2pt,
                           float* __restrict__ out) {
    int gw = (blockIdx.x * blockDim.x + threadIdx.x) >> 5;
    int lane = threadIdx.x & 31;
    if (gw >= BB * 128) return;
    int k = gw % 128, b = gw / 128;
    float* o = out + (size_t)gw * 259;
    for (int c = lane; c < 259; c += 32) {
        float v = (c < 3) ? l2xyz[(size_t)b * 384 + c * 128 + k]
                          : l2pt[((size_t)b * 128 + k) * 256 + (c - 3)];
        o[c] = v;
    }
}

// ---------------- GEMM: C = A(RxCIN) * W(CINxCOUT) + bias ----------------
template <int CIN, int COUT, int TR, int PC>
__global__ void gemm_t(const float* __restrict__ A, const float* __restrict__ W,
                       const float* __restrict__ bias, float* __restrict__ out) {
    constexpr int COLT = COUT / PC;
    constexpr int ROWT = 256 / COLT;
    constexpr int PR = TR / ROWT;
    constexpr int KC = 32;
    extern __shared__ float sm[];
    float* As = sm;
    float* Ws = sm + TR * CIN;
    int tid = threadIdx.x;
    int ct = tid % COLT, rt = tid / COLT;
    size_t row0 = (size_t)blockIdx.x * TR;
    float acc[PR][PC];
#pragma unroll
    for (int i = 0; i < PR; i++)
#pragma unroll
        for (int j = 0; j < PC; j++) acc[i][j] = 0.f;
    for (int e = tid; e < TR * CIN; e += 256) As[e] = A[row0 * CIN + e];
    for (int k0 = 0; k0 < CIN; k0 += KC) {
        int kc = (CIN - k0 < KC) ? (CIN - k0) : KC;
        __syncthreads();
        for (int e = tid; e < kc * COUT; e += 256) Ws[e] = W[(size_t)k0 * COUT + e];
        __syncthreads();
        for (int kk = 0; kk < kc; kk++) {
            float wr[PC];
#pragma unroll
            for (int j = 0; j < PC; j++) wr[j] = Ws[kk * COUT + ct * PC + j];
            float ar[PR];
#pragma unroll
            for (int i = 0; i < PR; i++) ar[i] = As[(rt * PR + i) * CIN + k0 + kk];
#pragma unroll
            for (int i = 0; i < PR; i++)
#pragma unroll
                for (int j = 0; j < PC; j++) acc[i][j] += ar[i] * wr[j];
        }
    }
#pragma unroll
    for (int i = 0; i < PR; i++) {
        size_t r = row0 + rt * PR + i;
#pragma unroll
        for (int j = 0; j < PC; j++) out[r * COUT + ct * PC + j] = acc[i][j] + bias[ct * PC + j];
    }
}

// ---------------- BatchNorm over all rows, per channel ----------------
__global__ void bn_zero_kernel() {
    int i = threadIdx.x;
    if (i < 512) { g_sum[i] = 0.0; g_sumsq[i] = 0.0; }
}

__global__ void bn_stats_kernel(const float* __restrict__ x, size_t total, int C) {
    __shared__ float ss[512], sq[512];
    for (int i = threadIdx.x; i < C; i += blockDim.x) { ss[i] = 0.f; sq[i] = 0.f; }
    __syncthreads();
    size_t stride = (size_t)gridDim.x * blockDim.x;
    for (size_t i = (size_t)blockIdx.x * blockDim.x + threadIdx.x; i < total; i += stride) {
        float v = x[i];
        int c = (int)(i & (size_t)(C - 1));
        atomicAdd(&ss[c], v);
        atomicAdd(&sq[c], v * v);
    }
    __syncthreads();
    for (int c = threadIdx.x; c < C; c += blockDim.x) {
        atomicAdd(&g_sum[c], (double)ss[c]);
        atomicAdd(&g_sumsq[c], (double)sq[c]);
    }
}

__global__ void bn_finalize_kernel(int C, double invcnt, const float* __restrict__ gamma,
                                   const float* __restrict__ beta) {
    int c = threadIdx.x;
    if (c >= C) return;
    double m = g_sum[c] * invcnt;
    double var = g_sumsq[c] * invcnt - m * m;
    float s = gamma[c] * rsqrtf((float)var + 1e-5f);
    g_scale[c] = s;
    g_shift[c] = beta[c] - (float)m * s;
}

__global__ void bn_apply_kernel(float* __restrict__ x, size_t total, int C) {
    size_t stride = (size_t)gridDim.x * blockDim.x;
    for (size_t i = (size_t)blockIdx.x * blockDim.x + threadIdx.x; i < total; i += stride) {
        int c = (int)(i & (size_t)(C - 1));
        x[i] = fmaxf(x[i] * g_scale[c] + g_shift[c], 0.f);
    }
}

// ---------------- maxpool over K ----------------
__global__ void maxpool_kernel(const float* __restrict__ x, int S, int K, int C,
                               float* __restrict__ out /*(B,C,S)*/,
                               float* __restrict__ outT /*(B*S,C) or null*/) {
    int total = BB * S * C;
    int stride = gridDim.x * blockDim.x;
    for (int i = blockIdx.x * blockDim.x + threadIdx.x; i < total; i += stride) {
        int c = i % C;
        int s = (i / C) % S;
        int b = i / (C * S);
        const float* p = x + ((size_t)(b * S + s) * K) * C + c;
        float m = p[0];
        for (int k = 1; k < K; k++) m = fmaxf(m, p[(size_t)k * C]);
        out[(size_t)b * C * S + (size_t)c * S + s] = m;
        if (outT) outT[(size_t)(b * S + s) * C + c] = m;
    }
}

__global__ void zero_kernel(float* p, int n) {
    int i = blockIdx.x * blockDim.x + threadIdx.x;
    if (i < n) p[i] = 0.f;
}

// ---------------- orchestration ----------------
extern "C" void kernel_launch(void* const* d_in, const int* in_sizes, int n_in,
                              void* d_out, int out_size) {
    (void)in_sizes; (void)n_in; (void)out_size;
    const float* l0_xyz = (const float*)d_in[0];
    const float* l0_pts = (const float*)d_in[1];
    float* out = (float*)d_out;

    float* o_l1xyz = out;                 // 16*3*256   = 12288
    float* o_l1pts = out + 12288;         // 16*128*256 = 524288
    float* o_l2xyz = out + 536576;        // 16*3*128   = 6144
    float* o_l2pts = out + 542720;        // 16*256*128 = 524288
    float* o_l3xyz = out + 1067008;       // 16*3*1     = 48
    float* o_x     = out + 1067056;       // 16*512     = 8192

    float *bufA, *bufB, *nxyz, *l1pt, *l2pt;
    int *fidx, *gi;
    cudaGetSymbolAddress((void**)&bufA, g_bufA);
    cudaGetSymbolAddress((void**)&bufB, g_bufB);
    cudaGetSymbolAddress((void**)&nxyz, g_newxyz);
    cudaGetSymbolAddress((void**)&l1pt, g_l1pt);
    cudaGetSymbolAddress((void**)&l2pt, g_l2pt);
    cudaGetSymbolAddress((void**)&fidx, g_fidx);
    cudaGetSymbolAddress((void**)&gi, g_gi);

    // dynamic smem opt-ins
    cudaFuncSetAttribute((const void*)fps_kernel, cudaFuncAttributeMaxDynamicSharedMemorySize, 65536);
    cudaFuncSetAttribute((const void*)gemm_t<131, 128, 32, 4>, cudaFuncAttributeMaxDynamicSharedMemorySize, 33152);
    cudaFuncSetAttribute((const void*)gemm_t<128, 256, 32, 4>, cudaFuncAttributeMaxDynamicSharedMemorySize, 49152);
    cudaFuncSetAttribute((const void*)gemm_t<259, 256, 32, 4>, cudaFuncAttributeMaxDynamicSharedMemorySize, 65920);
    cudaFuncSetAttribute((const void*)gemm_t<256, 512, 32, 8>, cudaFuncAttributeMaxDynamicSharedMemorySize, 98304);

    auto run_bn = [&](float* buf, size_t rows, int C, int gidx, int bidx) {
        bn_zero_kernel<<<1, 512>>>();
        bn_stats_kernel<<<2048, 256>>>(buf, rows * (size_t)C, C);
        bn_finalize_kernel<<<1, 512>>>(C, 1.0 / (double)rows,
                                       (const float*)d_in[gidx], (const float*)d_in[bidx]);
        bn_apply_kernel<<<2048, 256>>>(buf, rows * (size_t)C, C);
    };

    // ================= SA1 : N=4096 -> S=256, K=32 =================
    fps_kernel<<<16, 512, 65536>>>(l0_xyz, 4096, 256, fidx, nxyz, o_l1xyz);
    ballquery_kernel<<<(16 * 256) / 8, 256>>>(l0_xyz, nxyz, 4096, 256, 32, 0.04f, gi);
    gather_sa1<<<512, 256>>>(l0_xyz, l0_pts, gi, nxyz, bufA);
    gemm_t<6, 64, 32, 2><<<131072 / 32, 256, 8960>>>(bufA, (const float*)d_in[2], (const float*)d_in[3], bufB);
    run_bn(bufB, 131072, 64, 4, 5);
    gemm_t<64, 128, 32, 4><<<131072 / 32, 256, 24576>>>(bufB, (const float*)d_in[6], (const float*)d_in[7], bufA);
    run_bn(bufA, 131072, 128, 8, 9);
    maxpool_kernel<<<2048, 256>>>(bufA, 256, 32, 128, o_l1pts, l1pt);

    // ================= SA2 : N=256 -> S=128, K=64 =================
    fps_kernel<<<16, 256, 4096>>>(o_l1xyz, 256, 128, fidx, nxyz, o_l2xyz);
    ballquery_kernel<<<(16 * 128) / 8, 256>>>(o_l1xyz, nxyz, 256, 128, 64, 0.0625f, gi);
    gather_sa2<<<16384, 256>>>(o_l1xyz, l1pt, gi, nxyz, bufA);
    gemm_t<131, 128, 32, 4><<<131072 / 32, 256, 33152>>>(bufA, (const float*)d_in[10], (const float*)d_in[11], bufB);
    run_bn(bufB, 131072, 128, 12, 13);
    gemm_t<128, 256, 32, 4><<<131072 / 32, 256, 49152>>>(bufB, (const float*)d_in[14], (const float*)d_in[15], bufA);
    run_bn(bufA, 131072, 256, 16, 17);
    maxpool_kernel<<<2048, 256>>>(bufA, 128, 64, 256, o_l2pts, l2pt);

    // ================= SA3 : group_all, K=128 =================
    gather_sa3<<<256, 256>>>(o_l2xyz, l2pt, bufA);
    gemm_t<259, 256, 32, 4><<<2048 / 32, 256, 65920>>>(bufA, (const float*)d_in[18], (const float*)d_in[19], bufB);
    run_bn(bufB, 2048, 256, 20, 21);
    gemm_t<256, 512, 32, 8><<<2048 / 32, 256, 98304>>>(bufB, (const float*)d_in[22], (const float*)d_in[23], bufA);
    run_bn(bufA, 2048, 512, 24, 25);
    maxpool_kernel<<<32, 256>>>(bufA, 1, 128, 512, o_x, nullptr);
    zero_kernel<<<1, 48>>>(o_l3xyz, 48);
}